// round 1
// baseline (speedup 1.0000x reference)
#include <cuda_runtime.h>
#include <cuda_bf16.h>
#include <cstdint>
#include <math.h>

#define B_ 4
#define T_ 4096
#define C_ 1024
#define H_ 128

// Scratch for projected Q, K, V ([B*T, H] fp32 each). Static device arrays:
// allocation-free per harness rules.
__device__ float g_Q[B_ * T_ * H_];
__device__ float g_K[B_ * T_ * H_];
__device__ float g_V[B_ * T_ * H_];

__device__ __forceinline__ uint32_t f2tf(float f) {
    uint32_t r;
    asm("cvt.rna.tf32.f32 %0, %1;" : "=r"(r) : "f"(f));
    return r;
}

// D += A(16x8, tf32) * B(8x8, tf32), fp32 accum
__device__ __forceinline__ void mma_tf32(float c[4], const uint32_t a[4], const uint32_t b[2]) {
    asm volatile(
        "mma.sync.aligned.m16n8k8.row.col.f32.tf32.tf32.f32 "
        "{%0,%1,%2,%3}, {%4,%5,%6,%7}, {%8,%9}, {%0,%1,%2,%3};"
        : "+f"(c[0]), "+f"(c[1]), "+f"(c[2]), "+f"(c[3])
        : "r"(a[0]), "r"(a[1]), "r"(a[2]), "r"(a[3]), "r"(b[0]), "r"(b[1]));
}

// ---------------------------------------------------------------------------
// Projection: out[16384,128] = x[16384,1024] @ W[1024,128]
// Grid: (128 m-tiles, 3 matrices). Block: 256 threads (8 warps).
// Per warp: 16 rows x 128 cols. K-chunks of 32.
// ---------------------------------------------------------------------------
__global__ __launch_bounds__(256)
void proj_kernel(const float* __restrict__ x,
                 const float* __restrict__ Wq,
                 const float* __restrict__ Wk,
                 const float* __restrict__ Wv)
{
    __shared__ float Xs[128 * 36];   // 128 rows x 32 cols, stride 36 (bank-safe)
    __shared__ float Ws[32 * 132];   // 32 rows x 128 cols, stride 132

    const int which = blockIdx.y;
    const float* __restrict__ W = (which == 0) ? Wq : (which == 1) ? Wk : Wv;
    float* __restrict__ out = (which == 0) ? g_Q : (which == 1) ? g_K : g_V;

    const int tid  = threadIdx.x;
    const int warp = tid >> 5;
    const int lane = tid & 31;
    const int g    = lane >> 2;
    const int t4   = lane & 3;
    const int m0   = blockIdx.x * 128;

    float acc[16][4];
#pragma unroll
    for (int i = 0; i < 16; i++)
#pragma unroll
        for (int j = 0; j < 4; j++) acc[i][j] = 0.f;

    for (int kb = 0; kb < C_; kb += 32) {
        __syncthreads();
        // X tile: 128x32 floats = 1024 float4, 4 per thread
#pragma unroll
        for (int r = 0; r < 4; r++) {
            int i   = tid + r * 256;
            int row = i >> 3;          // 8 float4 per row
            int c4  = i & 7;
            float4 v = *reinterpret_cast<const float4*>(
                &x[(size_t)(m0 + row) * C_ + kb + c4 * 4]);
            *reinterpret_cast<float4*>(&Xs[row * 36 + c4 * 4]) = v;
        }
        // W tile: 32x128 floats = 1024 float4
#pragma unroll
        for (int r = 0; r < 4; r++) {
            int i   = tid + r * 256;
            int row = i >> 5;          // 32 float4 per row
            int c4  = i & 31;
            float4 v = *reinterpret_cast<const float4*>(
                &W[(size_t)(kb + row) * H_ + c4 * 4]);
            *reinterpret_cast<float4*>(&Ws[row * 132 + c4 * 4]) = v;
        }
        __syncthreads();

#pragma unroll
        for (int kk = 0; kk < 4; kk++) {
            uint32_t a[4];
            int r0 = warp * 16 + g;
            a[0] = f2tf(Xs[r0 * 36 + kk * 8 + t4]);
            a[1] = f2tf(Xs[(r0 + 8) * 36 + kk * 8 + t4]);
            a[2] = f2tf(Xs[r0 * 36 + kk * 8 + t4 + 4]);
            a[3] = f2tf(Xs[(r0 + 8) * 36 + kk * 8 + t4 + 4]);
#pragma unroll
            for (int nb = 0; nb < 16; nb++) {
                uint32_t b[2];
                b[0] = f2tf(Ws[(kk * 8 + t4) * 132 + nb * 8 + g]);
                b[1] = f2tf(Ws[(kk * 8 + t4 + 4) * 132 + nb * 8 + g]);
                mma_tf32(acc[nb], a, b);
            }
        }
    }

    // epilogue
    const int r0 = m0 + warp * 16 + g;
#pragma unroll
    for (int nb = 0; nb < 16; nb++) {
        int c = nb * 8 + 2 * t4;
        out[(size_t)r0 * H_ + c]           = acc[nb][0];
        out[(size_t)r0 * H_ + c + 1]       = acc[nb][1];
        out[(size_t)(r0 + 8) * H_ + c]     = acc[nb][2];
        out[(size_t)(r0 + 8) * H_ + c + 1] = acc[nb][3];
    }
}

// ---------------------------------------------------------------------------
// Flash attention: per CTA one (batch, 128-query tile), sweep KV in tiles of 32.
// Block: 256 threads (8 warps), each warp owns 16 query rows.
// Q held in registers as tf32 A-fragments. P routed through smem (overlaid on
// the K tile) to form A-fragments for the PV MMA.
// ---------------------------------------------------------------------------
__global__ __launch_bounds__(256)
void attn_kernel(float* __restrict__ out)
{
    __shared__ float KP[32 * 132];   // K tile [32][132]; reused as P [128][33]
    __shared__ float Vs[32 * 132];   // V tile [32][132]

    const int tid  = threadIdx.x;
    const int warp = tid >> 5;
    const int lane = tid & 31;
    const int g    = lane >> 2;
    const int t4   = lane & 3;
    const int b    = blockIdx.y;
    const int q0   = blockIdx.x * 128;

    const float* __restrict__ Q = g_Q + (size_t)b * T_ * H_;
    const float* __restrict__ K = g_K + (size_t)b * T_ * H_;
    const float* __restrict__ V = g_V + (size_t)b * T_ * H_;

    // Preload Q as A-fragments (rows rg, rg+8; 16 k-steps of 8)
    uint32_t qa[16][4];
    const int rg  = q0 + warp * 16 + g;
    const int rg8 = rg + 8;
#pragma unroll
    for (int kk = 0; kk < 16; kk++) {
        qa[kk][0] = f2tf(Q[(size_t)rg * H_ + kk * 8 + t4]);
        qa[kk][1] = f2tf(Q[(size_t)rg8 * H_ + kk * 8 + t4]);
        qa[kk][2] = f2tf(Q[(size_t)rg * H_ + kk * 8 + t4 + 4]);
        qa[kk][3] = f2tf(Q[(size_t)rg8 * H_ + kk * 8 + t4 + 4]);
    }

    float o[16][4];
#pragma unroll
    for (int i = 0; i < 16; i++)
#pragma unroll
        for (int j = 0; j < 4; j++) o[i][j] = 0.f;

    float mrun[2] = {-INFINITY, -INFINITY};
    float lsum[2] = {0.f, 0.f};
    const float scale = 0.03125f;   // C^-0.5 = 1024^-0.5

    for (int kv = 0; kv < T_; kv += 32) {
        __syncthreads();   // previous iter's P / V reads complete
        // Load K, V tiles: each 32x128 floats = 1024 float4
#pragma unroll
        for (int r = 0; r < 4; r++) {
            int i   = tid + r * 256;
            int row = i >> 5;
            int c4  = i & 31;
            float4 kvv = *reinterpret_cast<const float4*>(
                &K[(size_t)(kv + row) * H_ + c4 * 4]);
            *reinterpret_cast<float4*>(&KP[row * 132 + c4 * 4]) = kvv;
            float4 vvv = *reinterpret_cast<const float4*>(
                &V[(size_t)(kv + row) * H_ + c4 * 4]);
            *reinterpret_cast<float4*>(&Vs[row * 132 + c4 * 4]) = vvv;
        }
        __syncthreads();

        // S = Q K^T : per warp 16x32 (4 n-tiles), k = 128 (16 steps)
        float s[4][4];
#pragma unroll
        for (int i = 0; i < 4; i++)
#pragma unroll
            for (int j = 0; j < 4; j++) s[i][j] = 0.f;
#pragma unroll
        for (int kk = 0; kk < 16; kk++) {
#pragma unroll
            for (int nb = 0; nb < 4; nb++) {
                uint32_t bf[2];
                bf[0] = f2tf(KP[(nb * 8 + g) * 132 + kk * 8 + t4]);
                bf[1] = f2tf(KP[(nb * 8 + g) * 132 + kk * 8 + t4 + 4]);
                mma_tf32(s[nb], qa[kk], bf);
            }
        }
        __syncthreads();   // all warps done reading K before P overwrite

        // Online softmax (rows g and g+8 per thread; quad = 4 lanes per row)
#pragma unroll
        for (int nb = 0; nb < 4; nb++)
#pragma unroll
            for (int j = 0; j < 4; j++) s[nb][j] *= scale;

        float alpha[2];
#pragma unroll
        for (int hr = 0; hr < 2; hr++) {
            float mx = -INFINITY;
#pragma unroll
            for (int nb = 0; nb < 4; nb++)
                mx = fmaxf(mx, fmaxf(s[nb][2 * hr], s[nb][2 * hr + 1]));
            mx = fmaxf(mx, __shfl_xor_sync(0xffffffffu, mx, 1));
            mx = fmaxf(mx, __shfl_xor_sync(0xffffffffu, mx, 2));
            float mn = fmaxf(mrun[hr], mx);
            alpha[hr] = __expf(mrun[hr] - mn);
            float sum = 0.f;
#pragma unroll
            for (int nb = 0; nb < 4; nb++) {
                s[nb][2 * hr]     = __expf(s[nb][2 * hr] - mn);
                s[nb][2 * hr + 1] = __expf(s[nb][2 * hr + 1] - mn);
                sum += s[nb][2 * hr] + s[nb][2 * hr + 1];
            }
            sum += __shfl_xor_sync(0xffffffffu, sum, 1);
            sum += __shfl_xor_sync(0xffffffffu, sum, 2);
            lsum[hr] = lsum[hr] * alpha[hr] + sum;
            mrun[hr] = mn;
        }
#pragma unroll
        for (int nb = 0; nb < 16; nb++) {
            o[nb][0] *= alpha[0]; o[nb][1] *= alpha[0];
            o[nb][2] *= alpha[1]; o[nb][3] *= alpha[1];
        }

        // P -> smem (warp-local rows; overlays K tile), stride 33
        float* P = KP;
        const int prg = warp * 16 + g;
#pragma unroll
        for (int nb = 0; nb < 4; nb++) {
            int c = nb * 8 + 2 * t4;
            P[prg * 33 + c]           = s[nb][0];
            P[prg * 33 + c + 1]       = s[nb][1];
            P[(prg + 8) * 33 + c]     = s[nb][2];
            P[(prg + 8) * 33 + c + 1] = s[nb][3];
        }
        __syncwarp();

        // O += P V : per warp 16x128 (16 n-tiles), k = 32 (4 steps)
#pragma unroll
        for (int kk = 0; kk < 4; kk++) {
            uint32_t a[4];
            a[0] = f2tf(P[prg * 33 + kk * 8 + t4]);
            a[1] = f2tf(P[(prg + 8) * 33 + kk * 8 + t4]);
            a[2] = f2tf(P[prg * 33 + kk * 8 + t4 + 4]);
            a[3] = f2tf(P[(prg + 8) * 33 + kk * 8 + t4 + 4]);
#pragma unroll
            for (int nb = 0; nb < 16; nb++) {
                uint32_t bf[2];
                bf[0] = f2tf(Vs[(kk * 8 + t4) * 132 + nb * 8 + g]);
                bf[1] = f2tf(Vs[(kk * 8 + t4 + 4) * 132 + nb * 8 + g]);
                mma_tf32(o[nb], a, bf);
            }
        }
    }

    // Epilogue: out = O / l
    const float inv0 = 1.f / lsum[0];
    const float inv1 = 1.f / lsum[1];
    const size_t orow  = (size_t)b * T_ * H_ + (size_t)(q0 + warp * 16 + g) * H_;
    const size_t orow8 = orow + (size_t)8 * H_;
#pragma unroll
    for (int nb = 0; nb < 16; nb++) {
        int c = nb * 8 + 2 * t4;
        out[orow + c]      = o[nb][0] * inv0;
        out[orow + c + 1]  = o[nb][1] * inv0;
        out[orow8 + c]     = o[nb][2] * inv1;
        out[orow8 + c + 1] = o[nb][3] * inv1;
    }
}

extern "C" void kernel_launch(void* const* d_in, const int* in_sizes, int n_in,
                              void* d_out, int out_size)
{
    (void)in_sizes; (void)n_in; (void)out_size;
    const float* x  = (const float*)d_in[0];
    const float* Wk = (const float*)d_in[1];
    const float* Wq = (const float*)d_in[2];
    const float* Wv = (const float*)d_in[3];
    float* out = (float*)d_out;

    dim3 pgrid(16384 / 128, 3);
    proj_kernel<<<pgrid, 256>>>(x, Wq, Wk, Wv);

    dim3 agrid(T_ / 128, B_);
    attn_kernel<<<agrid, 256>>>(out);
}

// round 2
// speedup vs baseline: 1.8542x; 1.8542x over previous
#include <cuda_runtime.h>
#include <cstdint>
#include <math.h>

#define B_ 4
#define T_ 4096
#define C_ 1024
#define H_ 128

// Projected Q, K, V ([B*T, H]) stored as tf32-rounded fp32 (MMA-ready).
__device__ float g_Q[B_ * T_ * H_];
__device__ float g_K[B_ * T_ * H_];
__device__ float g_V[B_ * T_ * H_];

__device__ __forceinline__ uint32_t f2tf(float f) {
    uint32_t r;
    asm("cvt.rna.tf32.f32 %0, %1;" : "=r"(r) : "f"(f));
    return r;
}
__device__ __forceinline__ float tfbits(float f) { return __uint_as_float(f2tf(f)); }

// D += A(16x8 tf32) * B(8x8 tf32), fp32 accum
__device__ __forceinline__ void mma_tf32(float c[4], const uint32_t a[4], const uint32_t b[2]) {
    asm volatile(
        "mma.sync.aligned.m16n8k8.row.col.f32.tf32.tf32.f32 "
        "{%0,%1,%2,%3}, {%4,%5,%6,%7}, {%8,%9}, {%0,%1,%2,%3};"
        : "+f"(c[0]), "+f"(c[1]), "+f"(c[2]), "+f"(c[3])
        : "r"(a[0]), "r"(a[1]), "r"(a[2]), "r"(a[3]), "r"(b[0]), "r"(b[1]));
}

// ---------------------------------------------------------------------------
// Projection: out[16384,128] = x[16384,1024] @ W[1024,128], stored tf32-rounded.
// Xs: pair-permuted columns (stride 40), A-frags = conflict-free LDS.64.
// Ws: natural layout (stride 136), b0/b1 scalar loads conflict-free.
// ---------------------------------------------------------------------------
__global__ __launch_bounds__(256)
void proj_kernel(const float* __restrict__ x,
                 const float* __restrict__ Wq,
                 const float* __restrict__ Wk,
                 const float* __restrict__ Wv)
{
    __shared__ float Xs[128 * 40];
    __shared__ float Ws[32 * 136];

    const int which = blockIdx.y;
    const float* __restrict__ W = (which == 0) ? Wq : (which == 1) ? Wk : Wv;
    float* __restrict__ out = (which == 0) ? g_Q : (which == 1) ? g_K : g_V;

    const int tid  = threadIdx.x;
    const int warp = tid >> 5;
    const int lane = tid & 31;
    const int g    = lane >> 2;
    const int t4   = lane & 3;
    const int m0   = blockIdx.x * 128;

    float acc[16][4];
#pragma unroll
    for (int i = 0; i < 16; i++)
#pragma unroll
        for (int j = 0; j < 4; j++) acc[i][j] = 0.f;

    for (int kb = 0; kb < C_; kb += 32) {
        __syncthreads();
        // Xs: 128 rows x 4 kk-pairs = 512 units, pair-interleaved store
#pragma unroll
        for (int it = 0; it < 2; it++) {
            int u = tid + it * 256;
            int row = u >> 2, kk = u & 3;
            const float4* xg = reinterpret_cast<const float4*>(
                x + (size_t)(m0 + row) * C_ + kb);
            float4 lo = xg[kk * 2], hi = xg[kk * 2 + 1];
            float4* dst = reinterpret_cast<float4*>(&Xs[row * 40 + kk * 8]);
            dst[0] = make_float4(tfbits(lo.x), tfbits(hi.x), tfbits(lo.y), tfbits(hi.y));
            dst[1] = make_float4(tfbits(lo.z), tfbits(hi.z), tfbits(lo.w), tfbits(hi.w));
        }
        // Ws: 32 rows x 32 float4 = 1024 units
#pragma unroll
        for (int it = 0; it < 4; it++) {
            int u = tid + it * 256;
            int row = u >> 5, c4 = u & 31;
            float4 v = *reinterpret_cast<const float4*>(
                &W[(size_t)(kb + row) * H_ + c4 * 4]);
            *reinterpret_cast<float4*>(&Ws[row * 136 + c4 * 4]) =
                make_float4(tfbits(v.x), tfbits(v.y), tfbits(v.z), tfbits(v.w));
        }
        __syncthreads();

#pragma unroll
        for (int kk = 0; kk < 4; kk++) {
            uint2 a02 = *reinterpret_cast<const uint2*>(
                &Xs[(warp * 16 + g) * 40 + kk * 8 + 2 * t4]);
            uint2 a13 = *reinterpret_cast<const uint2*>(
                &Xs[(warp * 16 + g + 8) * 40 + kk * 8 + 2 * t4]);
            uint32_t a[4] = {a02.x, a13.x, a02.y, a13.y};
#pragma unroll
            for (int nb = 0; nb < 16; nb++) {
                uint32_t b[2];
                b[0] = __float_as_uint(Ws[(kk * 8 + t4) * 136 + nb * 8 + g]);
                b[1] = __float_as_uint(Ws[(kk * 8 + t4 + 4) * 136 + nb * 8 + g]);
                mma_tf32(acc[nb], a, b);
            }
        }
    }

    const int r0 = m0 + warp * 16 + g;
#pragma unroll
    for (int nb = 0; nb < 16; nb++) {
        int c = nb * 8 + 2 * t4;
        out[(size_t)r0 * H_ + c]           = tfbits(acc[nb][0]);
        out[(size_t)r0 * H_ + c + 1]       = tfbits(acc[nb][1]);
        out[(size_t)(r0 + 8) * H_ + c]     = tfbits(acc[nb][2]);
        out[(size_t)(r0 + 8) * H_ + c + 1] = tfbits(acc[nb][3]);
    }
}

// ---------------------------------------------------------------------------
// Flash attention. CTA = (batch, 128 q-rows), KV tile 64, 8 warps x 16 rows.
// Kt: pair-permuted cols, stride 136 -> QK B-frag = conflict-free LDS.64.
// Vs: natural, stride 136 -> PV b0/b1 scalar loads conflict-free.
// Ps: pair-permuted cols, stride 72 -> PV A-frag = conflict-free LDS.64.
// All smem data already tf32 (no cvt on hot path).
// ---------------------------------------------------------------------------
#define KT_STRIDE 136
#define PS_STRIDE 72
#define ATTN_SMEM ((64 * KT_STRIDE * 2 + 128 * PS_STRIDE) * 4)   // 106496 B

__global__ __launch_bounds__(256)
void attn_kernel(float* __restrict__ out)
{
    extern __shared__ float sm[];
    float* Kt = sm;                       // [64][136]
    float* Vs = sm + 64 * KT_STRIDE;      // [64][136]
    float* Ps = Vs + 64 * KT_STRIDE;      // [128][72]

    const int tid  = threadIdx.x;
    const int warp = tid >> 5;
    const int lane = tid & 31;
    const int g    = lane >> 2;
    const int t4   = lane & 3;
    const int b    = blockIdx.y;
    const int q0   = blockIdx.x * 128;

    const float* __restrict__ Q = g_Q + (size_t)b * T_ * H_;
    const float* __restrict__ K = g_K + (size_t)b * T_ * H_;
    const float* __restrict__ V = g_V + (size_t)b * T_ * H_;

    // Q fragments (already tf32 bits)
    uint32_t qa[16][4];
    const int rg  = q0 + warp * 16 + g;
    const int rg8 = rg + 8;
#pragma unroll
    for (int kk = 0; kk < 16; kk++) {
        qa[kk][0] = __float_as_uint(Q[(size_t)rg  * H_ + kk * 8 + t4]);
        qa[kk][1] = __float_as_uint(Q[(size_t)rg8 * H_ + kk * 8 + t4]);
        qa[kk][2] = __float_as_uint(Q[(size_t)rg  * H_ + kk * 8 + t4 + 4]);
        qa[kk][3] = __float_as_uint(Q[(size_t)rg8 * H_ + kk * 8 + t4 + 4]);
    }

    float o[16][4];
#pragma unroll
    for (int i = 0; i < 16; i++)
#pragma unroll
        for (int j = 0; j < 4; j++) o[i][j] = 0.f;

    float mrun[2] = {-INFINITY, -INFINITY};
    float lsum[2] = {0.f, 0.f};
    const float SC = 0.04508422f;   // (1/sqrt(1024)) * log2(e) -> exp2 domain
    const int prow0 = warp * 16 + g;

    for (int kv = 0; kv < T_; kv += 64) {
        __syncthreads();   // prior tile's Kt/Vs/Ps reads complete

        // Kt fill: 64 rows x 16 kk-pairs, pair-interleaved (pure copy, no cvt)
        const float4* Kg = reinterpret_cast<const float4*>(K + (size_t)kv * H_);
#pragma unroll
        for (int it = 0; it < 4; it++) {
            int u = tid + it * 256;
            int row = u >> 4, kk = u & 15;
            float4 lo = Kg[row * 32 + kk * 2], hi = Kg[row * 32 + kk * 2 + 1];
            float4* dst = reinterpret_cast<float4*>(&Kt[row * KT_STRIDE + kk * 8]);
            dst[0] = make_float4(lo.x, hi.x, lo.y, hi.y);
            dst[1] = make_float4(lo.z, hi.z, lo.w, hi.w);
        }
        // Vs fill: straight float4 copy
        const float4* Vg = reinterpret_cast<const float4*>(V + (size_t)kv * H_);
#pragma unroll
        for (int it = 0; it < 8; it++) {
            int u = tid + it * 256;
            int row = u >> 5, c4 = u & 31;
            *reinterpret_cast<float4*>(&Vs[row * KT_STRIDE + c4 * 4]) = Vg[row * 32 + c4];
        }
        __syncthreads();

        // S = Q K^T : 16x64 per warp (8 n-tiles), k=128
        float s[8][4];
#pragma unroll
        for (int i = 0; i < 8; i++)
#pragma unroll
            for (int j = 0; j < 4; j++) s[i][j] = 0.f;
#pragma unroll
        for (int kk = 0; kk < 16; kk++) {
#pragma unroll
            for (int nb = 0; nb < 8; nb++) {
                uint2 bb = *reinterpret_cast<const uint2*>(
                    &Kt[(nb * 8 + g) * KT_STRIDE + kk * 8 + 2 * t4]);
                uint32_t bfr[2] = {bb.x, bb.y};
                mma_tf32(s[nb], qa[kk], bfr);
            }
        }

        // Online softmax in exp2 domain
#pragma unroll
        for (int nb = 0; nb < 8; nb++)
#pragma unroll
            for (int j = 0; j < 4; j++) s[nb][j] *= SC;

        float alpha[2];
#pragma unroll
        for (int hr = 0; hr < 2; hr++) {
            float mx = -INFINITY;
#pragma unroll
            for (int nb = 0; nb < 8; nb++)
                mx = fmaxf(mx, fmaxf(s[nb][2 * hr], s[nb][2 * hr + 1]));
            mx = fmaxf(mx, __shfl_xor_sync(0xffffffffu, mx, 1));
            mx = fmaxf(mx, __shfl_xor_sync(0xffffffffu, mx, 2));
            float mn = fmaxf(mrun[hr], mx);
            alpha[hr] = exp2f(mrun[hr] - mn);
            float sum = 0.f;
#pragma unroll
            for (int nb = 0; nb < 8; nb++) {
                s[nb][2 * hr]     = exp2f(s[nb][2 * hr] - mn);
                s[nb][2 * hr + 1] = exp2f(s[nb][2 * hr + 1] - mn);
                sum += s[nb][2 * hr] + s[nb][2 * hr + 1];
            }
            sum += __shfl_xor_sync(0xffffffffu, sum, 1);
            sum += __shfl_xor_sync(0xffffffffu, sum, 2);
            lsum[hr] = lsum[hr] * alpha[hr] + sum;
            mrun[hr] = mn;
        }
#pragma unroll
        for (int nb = 0; nb < 16; nb++) {
            o[nb][0] *= alpha[0]; o[nb][1] *= alpha[0];
            o[nb][2] *= alpha[1]; o[nb][3] *= alpha[1];
        }

        // P -> Ps (tf32, pair-permuted cols); warp-private rows
        const int pc0 = (t4 < 2) ? 4 * t4 : 4 * t4 - 7;
#pragma unroll
        for (int nb = 0; nb < 8; nb++) {
            float* p0 = &Ps[prow0 * PS_STRIDE + nb * 8 + pc0];
            float* p1 = &Ps[(prow0 + 8) * PS_STRIDE + nb * 8 + pc0];
            p0[0] = tfbits(s[nb][0]); p0[2] = tfbits(s[nb][1]);
            p1[0] = tfbits(s[nb][2]); p1[2] = tfbits(s[nb][3]);
        }
        __syncwarp();

        // O += P V : k=64 (8 steps), 16 n-tiles
#pragma unroll
        for (int kk = 0; kk < 8; kk++) {
            uint2 a02 = *reinterpret_cast<const uint2*>(
                &Ps[prow0 * PS_STRIDE + kk * 8 + 2 * t4]);
            uint2 a13 = *reinterpret_cast<const uint2*>(
                &Ps[(prow0 + 8) * PS_STRIDE + kk * 8 + 2 * t4]);
            uint32_t a[4] = {a02.x, a13.x, a02.y, a13.y};
#pragma unroll
            for (int nb = 0; nb < 16; nb++) {
                uint32_t bfr[2];
                bfr[0] = __float_as_uint(Vs[(kk * 8 + t4) * KT_STRIDE + nb * 8 + g]);
                bfr[1] = __float_as_uint(Vs[(kk * 8 + t4 + 4) * KT_STRIDE + nb * 8 + g]);
                mma_tf32(o[nb], a, bfr);
            }
        }
    }

    // Epilogue
    const float inv0 = 1.f / lsum[0];
    const float inv1 = 1.f / lsum[1];
    const size_t orow  = (size_t)b * T_ * H_ + (size_t)(q0 + warp * 16 + g) * H_;
    const size_t orow8 = orow + (size_t)8 * H_;
#pragma unroll
    for (int nb = 0; nb < 16; nb++) {
        int c = nb * 8 + 2 * t4;
        out[orow + c]      = o[nb][0] * inv0;
        out[orow + c + 1]  = o[nb][1] * inv0;
        out[orow8 + c]     = o[nb][2] * inv1;
        out[orow8 + c + 1] = o[nb][3] * inv1;
    }
}

extern "C" void kernel_launch(void* const* d_in, const int* in_sizes, int n_in,
                              void* d_out, int out_size)
{
    (void)in_sizes; (void)n_in; (void)out_size;
    const float* x  = (const float*)d_in[0];
    const float* Wk = (const float*)d_in[1];
    const float* Wq = (const float*)d_in[2];
    const float* Wv = (const float*)d_in[3];
    float* out = (float*)d_out;

    cudaFuncSetAttribute(attn_kernel,
                         cudaFuncAttributeMaxDynamicSharedMemorySize, ATTN_SMEM);

    dim3 pgrid(16384 / 128, 3);
    proj_kernel<<<pgrid, 256>>>(x, Wq, Wk, Wv);

    dim3 agrid(T_ / 128, B_);
    attn_kernel<<<agrid, 256, ATTN_SMEM>>>(out);
}

// round 3
// speedup vs baseline: 3.3951x; 1.8311x over previous
#include <cuda_runtime.h>
#include <cuda_fp16.h>
#include <cstdint>
#include <math.h>

#define B_ 4
#define T_ 4096
#define C_ 1024
#define H_ 128

// Projected Q, K, V as fp16, MMA-ready.
__device__ __half g_Q[B_ * T_ * H_];
__device__ __half g_K[B_ * T_ * H_];
__device__ __half g_V[B_ * T_ * H_];

// ---- PTX helpers -----------------------------------------------------------
__device__ __forceinline__ void mma_f16(float c[4], const uint32_t a[4],
                                        uint32_t b0, uint32_t b1) {
    asm volatile(
        "mma.sync.aligned.m16n8k16.row.col.f32.f16.f16.f32 "
        "{%0,%1,%2,%3}, {%4,%5,%6,%7}, {%8,%9}, {%0,%1,%2,%3};"
        : "+f"(c[0]), "+f"(c[1]), "+f"(c[2]), "+f"(c[3])
        : "r"(a[0]), "r"(a[1]), "r"(a[2]), "r"(a[3]), "r"(b0), "r"(b1));
}
__device__ __forceinline__ void ldsm4(uint32_t& r0, uint32_t& r1, uint32_t& r2,
                                      uint32_t& r3, uint32_t addr) {
    asm volatile("ldmatrix.sync.aligned.m8n8.x4.shared.b16 {%0,%1,%2,%3}, [%4];"
                 : "=r"(r0), "=r"(r1), "=r"(r2), "=r"(r3) : "r"(addr));
}
__device__ __forceinline__ void ldsm4t(uint32_t& r0, uint32_t& r1, uint32_t& r2,
                                       uint32_t& r3, uint32_t addr) {
    asm volatile("ldmatrix.sync.aligned.m8n8.x4.trans.shared.b16 {%0,%1,%2,%3}, [%4];"
                 : "=r"(r0), "=r"(r1), "=r"(r2), "=r"(r3) : "r"(addr));
}
__device__ __forceinline__ void cp16(uint32_t dst, const void* src) {
    asm volatile("cp.async.cg.shared.global [%0], [%1], 16;" :: "r"(dst), "l"(src));
}
__device__ __forceinline__ uint32_t h2u(__half2 h) { return *reinterpret_cast<uint32_t*>(&h); }

// ---------------------------------------------------------------------------
// Projection: out[16384,128](fp16) = x[16384,1024] @ W[1024,128]
// CTA: 128 rows, 8 warps (warp = 16 rows x 128 cols). K-chunk 64.
// Xs [128][72] half (A, ldmatrix), Ws [64][136] half (B, ldmatrix.trans).
// ---------------------------------------------------------------------------
#define XS_ST 72
#define WS_ST 136

__global__ __launch_bounds__(256)
void proj_kernel(const float* __restrict__ x,
                 const float* __restrict__ Wq,
                 const float* __restrict__ Wk,
                 const float* __restrict__ Wv)
{
    __shared__ __half Xs[128 * XS_ST];
    __shared__ __half Ws[64 * WS_ST];

    const int which = blockIdx.y;
    const float* __restrict__ W = (which == 0) ? Wq : (which == 1) ? Wk : Wv;
    __half* __restrict__ out = (which == 0) ? g_Q : (which == 1) ? g_K : g_V;

    const int tid  = threadIdx.x;
    const int warp = tid >> 5;
    const int lane = tid & 31;
    const int g    = lane >> 2;
    const int t4   = lane & 3;
    const int m0   = blockIdx.x * 128;

    const uint32_t xs_b = (uint32_t)__cvta_generic_to_shared(Xs);
    const uint32_t ws_b = (uint32_t)__cvta_generic_to_shared(Ws);
    // ldmatrix lane offsets (in halves)
    const int aoff = ((lane & 8) + (lane & 7)) * XS_ST + ((lane & 16) >> 1);
    const int woff = ((lane & 8) + (lane & 7)) * WS_ST + ((lane & 16) >> 1);

    float acc[16][4];
#pragma unroll
    for (int i = 0; i < 16; i++)
#pragma unroll
        for (int j = 0; j < 4; j++) acc[i][j] = 0.f;

    for (int kb = 0; kb < C_; kb += 64) {
        __syncthreads();
        // Xs: 128 rows x 64 halves; unit = 4 elems (float4 -> 2 half2)
#pragma unroll
        for (int it = 0; it < 8; it++) {
            int u = tid + it * 256;
            int row = u >> 4, q = u & 15;
            float4 v = *reinterpret_cast<const float4*>(
                &x[(size_t)(m0 + row) * C_ + kb + q * 4]);
            __half2 h01 = __floats2half2_rn(v.x, v.y);
            __half2 h23 = __floats2half2_rn(v.z, v.w);
            *reinterpret_cast<uint2*>(&Xs[row * XS_ST + q * 4]) =
                make_uint2(h2u(h01), h2u(h23));
        }
        // Ws: 64 rows x 128 halves
#pragma unroll
        for (int it = 0; it < 8; it++) {
            int u = tid + it * 256;
            int row = u >> 5, q = u & 31;
            float4 v = *reinterpret_cast<const float4*>(
                &W[(size_t)(kb + row) * H_ + q * 4]);
            __half2 h01 = __floats2half2_rn(v.x, v.y);
            __half2 h23 = __floats2half2_rn(v.z, v.w);
            *reinterpret_cast<uint2*>(&Ws[row * WS_ST + q * 4]) =
                make_uint2(h2u(h01), h2u(h23));
        }
        __syncthreads();

#pragma unroll
        for (int kk = 0; kk < 4; kk++) {
            uint32_t a[4];
            ldsm4(a[0], a[1], a[2], a[3],
                  xs_b + (warp * 16 * XS_ST + kk * 16 + aoff) * 2);
#pragma unroll
            for (int nbp = 0; nbp < 8; nbp++) {
                uint32_t b0, b1, b2, b3;
                ldsm4t(b0, b1, b2, b3,
                       ws_b + (kk * 16 * WS_ST + nbp * 16 + woff) * 2);
                mma_f16(acc[2 * nbp],     a, b0, b1);
                mma_f16(acc[2 * nbp + 1], a, b2, b3);
            }
        }
    }

    const int r0 = m0 + warp * 16 + g;
#pragma unroll
    for (int nb = 0; nb < 16; nb++) {
        int c = nb * 8 + 2 * t4;
        *reinterpret_cast<uint32_t*>(&out[(size_t)r0 * H_ + c]) =
            h2u(__floats2half2_rn(acc[nb][0], acc[nb][1]));
        *reinterpret_cast<uint32_t*>(&out[(size_t)(r0 + 8) * H_ + c]) =
            h2u(__floats2half2_rn(acc[nb][2], acc[nb][3]));
    }
}

// ---------------------------------------------------------------------------
// Flash attention, fp16 tiles. CTA = (batch, 128 q-rows), 8 warps, KV tile 64,
// double-buffered K/V via cp.async. ldmatrix for all fragments.
// ---------------------------------------------------------------------------
#define KT 136                       // halves per K/V row
#define PS 72                        // halves per P row
#define K0H 0
#define K1H (64 * KT)                // 8704
#define V0H (2 * 64 * KT)            // 17408
#define V1H (3 * 64 * KT)            // 26112
#define PSH (4 * 64 * KT)            // 34816
#define ATTN_SMEM ((PSH + 128 * PS) * 2)   // 88064 bytes

__global__ __launch_bounds__(256)
void attn_kernel(float* __restrict__ out)
{
    extern __shared__ __half sm[];
    const uint32_t sm_b = (uint32_t)__cvta_generic_to_shared(sm);

    const int tid  = threadIdx.x;
    const int warp = tid >> 5;
    const int lane = tid & 31;
    const int g    = lane >> 2;
    const int t4   = lane & 3;
    const int b    = blockIdx.y;
    const int q0   = blockIdx.x * 128;

    const __half* __restrict__ Q = g_Q + (size_t)b * T_ * H_;
    const __half* __restrict__ K = g_K + (size_t)b * T_ * H_;
    const __half* __restrict__ V = g_V + (size_t)b * T_ * H_;

    // ldmatrix lane offsets (halves)
    const int koff = (((lane & 16) >> 1) + (lane & 7)) * KT + ((lane & 8) ? 8 : 0);
    const int voff = ((lane & 8) + (lane & 7)) * KT + ((lane & 16) >> 1);
    const int aoff = ((lane & 8) + (lane & 7)) * PS + ((lane & 16) >> 1);

    // Q fragments: 8 k-steps x 4 regs (half2 each), direct global loads
    uint32_t qa[8][4];
    const int rg  = q0 + warp * 16 + g;
    const int rg8 = rg + 8;
#pragma unroll
    for (int kk = 0; kk < 8; kk++) {
        qa[kk][0] = *reinterpret_cast<const uint32_t*>(&Q[(size_t)rg  * H_ + kk * 16 + 2 * t4]);
        qa[kk][1] = *reinterpret_cast<const uint32_t*>(&Q[(size_t)rg8 * H_ + kk * 16 + 2 * t4]);
        qa[kk][2] = *reinterpret_cast<const uint32_t*>(&Q[(size_t)rg  * H_ + kk * 16 + 2 * t4 + 8]);
        qa[kk][3] = *reinterpret_cast<const uint32_t*>(&Q[(size_t)rg8 * H_ + kk * 16 + 2 * t4 + 8]);
    }

    float o[16][4];
#pragma unroll
    for (int i = 0; i < 16; i++)
#pragma unroll
        for (int j = 0; j < 4; j++) o[i][j] = 0.f;

    float mrun[2] = {-INFINITY, -INFINITY};
    float lsum[2] = {0.f, 0.f};
    const float SC = 0.04508422f;     // 1024^-0.5 * log2(e)
    const int prow0 = warp * 16 + g;

    // cp.async tile fill: 4 K-chunks + 4 V-chunks per thread (16 B each)
    auto issue_tile = [&](int kv, int stg) {
        const __half* Ksrc = K + (size_t)kv * H_;
        const __half* Vsrc = V + (size_t)kv * H_;
        uint32_t kb_ = sm_b + (stg ? K1H : K0H) * 2;
        uint32_t vb_ = sm_b + (stg ? V1H : V0H) * 2;
#pragma unroll
        for (int it = 0; it < 4; it++) {
            int u = tid + it * 256;
            int row = u >> 4, q = u & 15;
            cp16(kb_ + (row * KT + q * 8) * 2, Ksrc + (size_t)row * H_ + q * 8);
            cp16(vb_ + (row * KT + q * 8) * 2, Vsrc + (size_t)row * H_ + q * 8);
        }
        asm volatile("cp.async.commit_group;");
    };

    const int NT = T_ / 64;
    issue_tile(0, 0);

    for (int i = 0; i < NT; i++) {
        if (i + 1 < NT) {
            issue_tile((i + 1) * 64, (i + 1) & 1);
            asm volatile("cp.async.wait_group 1;");
        } else {
            asm volatile("cp.async.wait_group 0;");
        }
        __syncthreads();

        const uint32_t kbh = (i & 1) ? K1H : K0H;
        const uint32_t vbh = (i & 1) ? V1H : V0H;

        // S = Q K^T : 16x64 per warp
        float s[8][4];
#pragma unroll
        for (int n = 0; n < 8; n++)
#pragma unroll
            for (int j = 0; j < 4; j++) s[n][j] = 0.f;
#pragma unroll
        for (int kk = 0; kk < 8; kk++) {
#pragma unroll
            for (int nbp = 0; nbp < 4; nbp++) {
                uint32_t b0, b1, b2, b3;
                ldsm4(b0, b1, b2, b3,
                      sm_b + (kbh + nbp * 16 * KT + kk * 16 + koff) * 2);
                mma_f16(s[2 * nbp],     qa[kk], b0, b1);
                mma_f16(s[2 * nbp + 1], qa[kk], b2, b3);
            }
        }

        // Online softmax (exp2 domain)
#pragma unroll
        for (int n = 0; n < 8; n++)
#pragma unroll
            for (int j = 0; j < 4; j++) s[n][j] *= SC;

        float alpha[2];
#pragma unroll
        for (int hr = 0; hr < 2; hr++) {
            float mx = -INFINITY;
#pragma unroll
            for (int n = 0; n < 8; n++)
                mx = fmaxf(mx, fmaxf(s[n][2 * hr], s[n][2 * hr + 1]));
            mx = fmaxf(mx, __shfl_xor_sync(0xffffffffu, mx, 1));
            mx = fmaxf(mx, __shfl_xor_sync(0xffffffffu, mx, 2));
            float mn = fmaxf(mrun[hr], mx);
            alpha[hr] = exp2f(mrun[hr] - mn);
            float sum = 0.f;
#pragma unroll
            for (int n = 0; n < 8; n++) {
                s[n][2 * hr]     = exp2f(s[n][2 * hr] - mn);
                s[n][2 * hr + 1] = exp2f(s[n][2 * hr + 1] - mn);
                sum += s[n][2 * hr] + s[n][2 * hr + 1];
            }
            sum += __shfl_xor_sync(0xffffffffu, sum, 1);
            sum += __shfl_xor_sync(0xffffffffu, sum, 2);
            lsum[hr] = lsum[hr] * alpha[hr] + sum;
            mrun[hr] = mn;
        }
#pragma unroll
        for (int n = 0; n < 16; n++) {
            o[n][0] *= alpha[0]; o[n][1] *= alpha[0];
            o[n][2] *= alpha[1]; o[n][3] *= alpha[1];
        }

        // P -> smem (fp16), warp-private rows
#pragma unroll
        for (int n = 0; n < 8; n++) {
            *reinterpret_cast<uint32_t*>(&sm[PSH + prow0 * PS + n * 8 + 2 * t4]) =
                h2u(__floats2half2_rn(s[n][0], s[n][1]));
            *reinterpret_cast<uint32_t*>(&sm[PSH + (prow0 + 8) * PS + n * 8 + 2 * t4]) =
                h2u(__floats2half2_rn(s[n][2], s[n][3]));
        }
        __syncwarp();

        // O += P V : k = 64 (4 k-steps), n = 128 (16 tiles)
#pragma unroll
        for (int kk = 0; kk < 4; kk++) {
            uint32_t a[4];
            ldsm4(a[0], a[1], a[2], a[3],
                  sm_b + (PSH + warp * 16 * PS + kk * 16 + aoff) * 2);
#pragma unroll
            for (int nbp = 0; nbp < 8; nbp++) {
                uint32_t b0, b1, b2, b3;
                ldsm4t(b0, b1, b2, b3,
                       sm_b + (vbh + kk * 16 * KT + nbp * 16 + voff) * 2);
                mma_f16(o[2 * nbp],     a, b0, b1);
                mma_f16(o[2 * nbp + 1], a, b2, b3);
            }
        }
        __syncthreads();   // all warps done with this stage before its refill
    }

    // Epilogue: out = O / l  (fp32)
    const float inv0 = 1.f / lsum[0];
    const float inv1 = 1.f / lsum[1];
    const size_t orow  = (size_t)b * T_ * H_ + (size_t)(q0 + warp * 16 + g) * H_;
    const size_t orow8 = orow + (size_t)8 * H_;
#pragma unroll
    for (int n = 0; n < 16; n++) {
        int c = n * 8 + 2 * t4;
        *reinterpret_cast<float2*>(&out[orow + c]) =
            make_float2(o[n][0] * inv0, o[n][1] * inv0);
        *reinterpret_cast<float2*>(&out[orow8 + c]) =
            make_float2(o[n][2] * inv1, o[n][3] * inv1);
    }
}

extern "C" void kernel_launch(void* const* d_in, const int* in_sizes, int n_in,
                              void* d_out, int out_size)
{
    (void)in_sizes; (void)n_in; (void)out_size;
    const float* x  = (const float*)d_in[0];
    const float* Wk = (const float*)d_in[1];
    const float* Wq = (const float*)d_in[2];
    const float* Wv = (const float*)d_in[3];
    float* out = (float*)d_out;

    cudaFuncSetAttribute(attn_kernel,
                         cudaFuncAttributeMaxDynamicSharedMemorySize, ATTN_SMEM);

    dim3 pgrid(16384 / 128, 3);
    proj_kernel<<<pgrid, 256>>>(x, Wq, Wk, Wv);

    dim3 agrid(T_ / 128, B_);
    attn_kernel<<<agrid, 256, ATTN_SMEM>>>(out);
}

// round 5
// speedup vs baseline: 3.7414x; 1.1020x over previous
#include <cuda_runtime.h>
#include <cuda_fp16.h>
#include <cstdint>
#include <math.h>

#define B_ 4
#define T_ 4096
#define C_ 1024
#define H_ 128

// fp16 staging (static: allocation-free per harness rules)
__device__ __half g_X [B_ * T_ * C_];     // x as fp16            [bt][k]
__device__ __half g_WT[3 * H_ * C_];      // W^T fp16             [which][n][k]
__device__ __half g_Q [B_ * T_ * H_];
__device__ __half g_K [B_ * T_ * H_];
__device__ __half g_V [B_ * T_ * H_];

__device__ __forceinline__ uint32_t h2u(__half2 h) { return *reinterpret_cast<uint32_t*>(&h); }

__device__ __forceinline__ void mma_f16(float c[4], const uint32_t a[4],
                                        uint32_t b0, uint32_t b1) {
    asm volatile(
        "mma.sync.aligned.m16n8k16.row.col.f32.f16.f16.f32 "
        "{%0,%1,%2,%3}, {%4,%5,%6,%7}, {%8,%9}, {%0,%1,%2,%3};"
        : "+f"(c[0]), "+f"(c[1]), "+f"(c[2]), "+f"(c[3])
        : "r"(a[0]), "r"(a[1]), "r"(a[2]), "r"(a[3]), "r"(b0), "r"(b1));
}
__device__ __forceinline__ void ldsm4(uint32_t& r0, uint32_t& r1, uint32_t& r2,
                                      uint32_t& r3, uint32_t addr) {
    asm volatile("ldmatrix.sync.aligned.m8n8.x4.shared.b16 {%0,%1,%2,%3}, [%4];"
                 : "=r"(r0), "=r"(r1), "=r"(r2), "=r"(r3) : "r"(addr));
}
__device__ __forceinline__ void ldsm4t(uint32_t& r0, uint32_t& r1, uint32_t& r2,
                                       uint32_t& r3, uint32_t addr) {
    asm volatile("ldmatrix.sync.aligned.m8n8.x4.trans.shared.b16 {%0,%1,%2,%3}, [%4];"
                 : "=r"(r0), "=r"(r1), "=r"(r2), "=r"(r3) : "r"(addr));
}
__device__ __forceinline__ void cp16(uint32_t dst, const void* src) {
    asm volatile("cp.async.cg.shared.global [%0], [%1], 16;" :: "r"(dst), "l"(src));
}
__device__ __forceinline__ uint32_t ex2_f16x2(uint32_t x) {
    uint32_t r;
    asm("ex2.approx.f16x2 %0, %1;" : "=r"(r) : "r"(x));
    return r;
}

// ---------------------------------------------------------------------------
// Conversion kernels (HBM bound, one-shot)
// ---------------------------------------------------------------------------
__global__ __launch_bounds__(256)
void cvt_x_kernel(const float* __restrict__ x)
{
    int i = (blockIdx.x * 256 + threadIdx.x) * 8;
    float4 a = *reinterpret_cast<const float4*>(x + i);
    float4 b = *reinterpret_cast<const float4*>(x + i + 4);
    uint4 o;
    o.x = h2u(__floats2half2_rn(a.x, a.y));
    o.y = h2u(__floats2half2_rn(a.z, a.w));
    o.z = h2u(__floats2half2_rn(b.x, b.y));
    o.w = h2u(__floats2half2_rn(b.z, b.w));
    *reinterpret_cast<uint4*>(&g_X[i]) = o;
}

__global__ __launch_bounds__(256)
void cvt_w_kernel(const float* __restrict__ Wq,
                  const float* __restrict__ Wk,
                  const float* __restrict__ Wv)
{
    int idx = blockIdx.x * 256 + threadIdx.x;       // 3*128*1024
    int which = idx >> 17;
    int r = idx & 131071;
    int n = r >> 10, k = r & 1023;
    const float* W = (which == 0) ? Wq : (which == 1) ? Wk : Wv;
    g_WT[idx] = __float2half(W[k * H_ + n]);
}

// ---------------------------------------------------------------------------
// Projection GEMM: out[16384,128](fp16) = X[.,1024] @ W  (B given as W^T [n][k])
// CTA = 128 m x 128 n; k chunks of 128, double-buffered cp.async.
// ---------------------------------------------------------------------------
#define PJ 136                          // halves per tile row
#define PJ_TILE (128 * PJ)              // halves per stage tile
#define PA0 0
#define PA1 PJ_TILE
#define PB0 (2 * PJ_TILE)
#define PB1 (3 * PJ_TILE)
#define PROJ_SMEM (4 * PJ_TILE * 2)     // 139264 B

__global__ __launch_bounds__(256)
void proj_kernel()
{
    extern __shared__ __half psm[];
    const uint32_t sm_b = (uint32_t)__cvta_generic_to_shared(psm);

    const int tid  = threadIdx.x;
    const int warp = tid >> 5;
    const int lane = tid & 31;
    const int g    = lane >> 2;
    const int t4   = lane & 3;
    const int m0   = blockIdx.x * 128;
    const int which = blockIdx.y;
    __half* __restrict__ outp = (which == 0) ? g_Q : (which == 1) ? g_K : g_V;
    const __half* __restrict__ Asrc = g_X + (size_t)m0 * C_;
    const __half* __restrict__ Bsrc = g_WT + (size_t)which * H_ * C_;

    // ldmatrix lane offsets (halves)
    const int aoff = ((lane & 8) + (lane & 7)) * PJ + ((lane & 16) >> 1);
    const int koff = (((lane & 16) >> 1) + (lane & 7)) * PJ + ((lane & 8) ? 8 : 0);

    float acc[16][4];
#pragma unroll
    for (int i = 0; i < 16; i++)
#pragma unroll
        for (int j = 0; j < 4; j++) acc[i][j] = 0.f;

    auto fill = [&](int kb, int stg) {
        uint32_t ab = sm_b + (stg ? PA1 : PA0) * 2;
        uint32_t bb = sm_b + (stg ? PB1 : PB0) * 2;
#pragma unroll
        for (int it = 0; it < 8; it++) {
            int u = tid + it * 256;
            int row = u >> 4, q = u & 15;
            cp16(ab + (row * PJ + q * 8) * 2, Asrc + (size_t)row * C_ + kb + q * 8);
            cp16(bb + (row * PJ + q * 8) * 2, Bsrc + (size_t)row * C_ + kb + q * 8);
        }
        asm volatile("cp.async.commit_group;");
    };

    fill(0, 0);
    for (int c = 0; c < 8; c++) {
        if (c + 1 < 8) {
            fill((c + 1) * 128, (c + 1) & 1);
            asm volatile("cp.async.wait_group 1;");
        } else {
            asm volatile("cp.async.wait_group 0;");
        }
        __syncthreads();

        const uint32_t ab = sm_b + ((c & 1) ? PA1 : PA0) * 2;
        const uint32_t bb = sm_b + ((c & 1) ? PB1 : PB0) * 2;
#pragma unroll
        for (int kk = 0; kk < 8; kk++) {
            uint32_t a[4];
            ldsm4(a[0], a[1], a[2], a[3],
                  ab + (warp * 16 * PJ + kk * 16 + aoff) * 2);
#pragma unroll
            for (int nbp = 0; nbp < 8; nbp++) {
                uint32_t b0, b1, b2, b3;
                ldsm4(b0, b1, b2, b3,
                      bb + (nbp * 16 * PJ + kk * 16 + koff) * 2);
                mma_f16(acc[2 * nbp],     a, b0, b1);
                mma_f16(acc[2 * nbp + 1], a, b2, b3);
            }
        }
        __syncthreads();
    }

    const int r0 = m0 + warp * 16 + g;
#pragma unroll
    for (int nb = 0; nb < 16; nb++) {
        int cc = nb * 8 + 2 * t4;
        *reinterpret_cast<uint32_t*>(&outp[(size_t)r0 * H_ + cc]) =
            h2u(__floats2half2_rn(acc[nb][0], acc[nb][1]));
        *reinterpret_cast<uint32_t*>(&outp[(size_t)(r0 + 8) * H_ + cc]) =
            h2u(__floats2half2_rn(acc[nb][2], acc[nb][3]));
    }
}

// ---------------------------------------------------------------------------
// Flash attention: CTA = (batch, 128 q-rows), 8 warps, KV tile 64,
// double-buffered cp.async. P stays in registers (S-frag == A-frag for fp16).
// ---------------------------------------------------------------------------
#define KT 136
#define K0H 0
#define K1H (64 * KT)
#define V0H (2 * 64 * KT)
#define V1H (3 * 64 * KT)
#define ATTN_SMEM (4 * 64 * KT * 2)    // 69632 B

__global__ __launch_bounds__(256)
void attn_kernel(float* __restrict__ out)
{
    extern __shared__ __half sm[];
    const uint32_t sm_b = (uint32_t)__cvta_generic_to_shared(sm);

    const int tid  = threadIdx.x;
    const int warp = tid >> 5;
    const int lane = tid & 31;
    const int g    = lane >> 2;
    const int t4   = lane & 3;
    const int b    = blockIdx.y;
    const int q0   = blockIdx.x * 128;

    const __half* __restrict__ Q = g_Q + (size_t)b * T_ * H_;
    const __half* __restrict__ K = g_K + (size_t)b * T_ * H_;
    const __half* __restrict__ V = g_V + (size_t)b * T_ * H_;

    const int koff = (((lane & 16) >> 1) + (lane & 7)) * KT + ((lane & 8) ? 8 : 0);
    const int voff = ((lane & 8) + (lane & 7)) * KT + ((lane & 16) >> 1);

    // Q fragments, direct global loads (fp16 bits)
    uint32_t qa[8][4];
    const int rg  = q0 + warp * 16 + g;
    const int rg8 = rg + 8;
#pragma unroll
    for (int kk = 0; kk < 8; kk++) {
        qa[kk][0] = *reinterpret_cast<const uint32_t*>(&Q[(size_t)rg  * H_ + kk * 16 + 2 * t4]);
        qa[kk][1] = *reinterpret_cast<const uint32_t*>(&Q[(size_t)rg8 * H_ + kk * 16 + 2 * t4]);
        qa[kk][2] = *reinterpret_cast<const uint32_t*>(&Q[(size_t)rg  * H_ + kk * 16 + 2 * t4 + 8]);
        qa[kk][3] = *reinterpret_cast<const uint32_t*>(&Q[(size_t)rg8 * H_ + kk * 16 + 2 * t4 + 8]);
    }

    float o[16][4];
#pragma unroll
    for (int i = 0; i < 16; i++)
#pragma unroll
        for (int j = 0; j < 4; j++) o[i][j] = 0.f;

    float mrun[2] = {-INFINITY, -INFINITY};
    float lsum[2] = {0.f, 0.f};
    const float SC = 0.04508422f;     // 1024^-0.5 * log2(e)

    auto issue_tile = [&](int kv, int stg) {
        const __half* Ksrc = K + (size_t)kv * H_;
        const __half* Vsrc = V + (size_t)kv * H_;
        uint32_t kb_ = sm_b + (stg ? K1H : K0H) * 2;
        uint32_t vb_ = sm_b + (stg ? V1H : V0H) * 2;
#pragma unroll
        for (int it = 0; it < 4; it++) {
            int u = tid + it * 256;
            int row = u >> 4, q = u & 15;
            cp16(kb_ + (row * KT + q * 8) * 2, Ksrc + (size_t)row * H_ + q * 8);
            cp16(vb_ + (row * KT + q * 8) * 2, Vsrc + (size_t)row * H_ + q * 8);
        }
        asm volatile("cp.async.commit_group;");
    };

    const int NT = T_ / 64;
    issue_tile(0, 0);

    for (int i = 0; i < NT; i++) {
        if (i + 1 < NT) {
            issue_tile((i + 1) * 64, (i + 1) & 1);
            asm volatile("cp.async.wait_group 1;");
        } else {
            asm volatile("cp.async.wait_group 0;");
        }
        __syncthreads();

        const uint32_t kbh = (i & 1) ? K1H : K0H;
        const uint32_t vbh = (i & 1) ? V1H : V0H;

        // S = Q K^T : 16x64 per warp
        float s[8][4];
#pragma unroll
        for (int n = 0; n < 8; n++)
#pragma unroll
            for (int j = 0; j < 4; j++) s[n][j] = 0.f;
#pragma unroll
        for (int kk = 0; kk < 8; kk++) {
#pragma unroll
            for (int nbp = 0; nbp < 4; nbp++) {
                uint32_t b0, b1, b2, b3;
                ldsm4(b0, b1, b2, b3,
                      sm_b + (kbh + nbp * 16 * KT + kk * 16 + koff) * 2);
                mma_f16(s[2 * nbp],     qa[kk], b0, b1);
                mma_f16(s[2 * nbp + 1], qa[kk], b2, b3);
            }
        }

        // Online softmax; exp via ex2.f16x2 -> P directly in fragment form
#pragma unroll
        for (int n = 0; n < 8; n++)
#pragma unroll
            for (int j = 0; j < 4; j++) s[n][j] *= SC;

        float alpha[2];
        uint32_t ph2[8][2];   // ph2[n][0] = row g (cols 2t4,2t4+1), [1] = row g+8
#pragma unroll
        for (int hr = 0; hr < 2; hr++) {
            float mx = -INFINITY;
#pragma unroll
            for (int n = 0; n < 8; n++)
                mx = fmaxf(mx, fmaxf(s[n][2 * hr], s[n][2 * hr + 1]));
            mx = fmaxf(mx, __shfl_xor_sync(0xffffffffu, mx, 1));
            mx = fmaxf(mx, __shfl_xor_sync(0xffffffffu, mx, 2));
            float mn = fmaxf(mrun[hr], mx);
            alpha[hr] = exp2f(mrun[hr] - mn);
            float sum = 0.f;
#pragma unroll
            for (int n = 0; n < 8; n++) {
                __half2 hh = __floats2half2_rn(s[n][2 * hr] - mn, s[n][2 * hr + 1] - mn);
                uint32_t e = ex2_f16x2(h2u(hh));
                ph2[n][hr] = e;
                float2 f = __half22float2(*reinterpret_cast<__half2*>(&e));
                sum += f.x + f.y;
            }
            sum += __shfl_xor_sync(0xffffffffu, sum, 1);
            sum += __shfl_xor_sync(0xffffffffu, sum, 2);
            lsum[hr] = lsum[hr] * alpha[hr] + sum;
            mrun[hr] = mn;
        }
#pragma unroll
        for (int n = 0; n < 16; n++) {
            o[n][0] *= alpha[0]; o[n][1] *= alpha[0];
            o[n][2] *= alpha[1]; o[n][3] *= alpha[1];
        }

        // O += P V : P already register-resident as A-fragments
#pragma unroll
        for (int kk = 0; kk < 4; kk++) {
            uint32_t a[4] = {ph2[2 * kk][0], ph2[2 * kk][1],
                             ph2[2 * kk + 1][0], ph2[2 * kk + 1][1]};
#pragma unroll
            for (int nbp = 0; nbp < 8; nbp++) {
                uint32_t b0, b1, b2, b3;
                ldsm4t(b0, b1, b2, b3,
                       sm_b + (vbh + kk * 16 * KT + nbp * 16 + voff) * 2);
                mma_f16(o[2 * nbp],     a, b0, b1);
                mma_f16(o[2 * nbp + 1], a, b2, b3);
            }
        }
        __syncthreads();   // stage fully consumed before its refill
    }

    const float inv0 = 1.f / lsum[0];
    const float inv1 = 1.f / lsum[1];
    const size_t orow  = (size_t)b * T_ * H_ + (size_t)(q0 + warp * 16 + g) * H_;
    const size_t orow8 = orow + (size_t)8 * H_;
#pragma unroll
    for (int n = 0; n < 16; n++) {
        int cc = n * 8 + 2 * t4;
        *reinterpret_cast<float2*>(&out[orow + cc]) =
            make_float2(o[n][0] * inv0, o[n][1] * inv0);
        *reinterpret_cast<float2*>(&out[orow8 + cc]) =
            make_float2(o[n][2] * inv1, o[n][3] * inv1);
    }
}

extern "C" void kernel_launch(void* const* d_in, const int* in_sizes, int n_in,
                              void* d_out, int out_size)
{
    (void)in_sizes; (void)n_in; (void)out_size;
    const float* x  = (const float*)d_in[0];
    const float* Wk = (const float*)d_in[1];
    const float* Wq = (const float*)d_in[2];
    const float* Wv = (const float*)d_in[3];
    float* out = (float*)d_out;

    cudaFuncSetAttribute(proj_kernel,
                         cudaFuncAttributeMaxDynamicSharedMemorySize, PROJ_SMEM);
    cudaFuncSetAttribute(attn_kernel,
                         cudaFuncAttributeMaxDynamicSharedMemorySize, ATTN_SMEM);

    cvt_x_kernel<<<B_ * T_ * C_ / (256 * 8), 256>>>(x);
    cvt_w_kernel<<<3 * H_ * C_ / 256, 256>>>(Wq, Wk, Wv);

    dim3 pgrid(16384 / 128, 3);
    proj_kernel<<<pgrid, 256, PROJ_SMEM>>>();

    dim3 agrid(T_ / 128, B_);
    attn_kernel<<<agrid, 256, ATTN_SMEM>>>(out);
}